// round 16
// baseline (speedup 1.0000x reference)
#include <cuda_runtime.h>
#include <cuda_fp16.h>
#include <math.h>
#include <stdint.h>

#define NB   4
#define C3   256
#define HW3  3136
#define HWP3 3200
#define C4   512
#define HW4  784
#define HWP4 896
#define EPSV 1e-5f
#define LOG2E 1.4426950408889634f
#define K2C   2.8853900817779268f   /* 2*log2(e) */

#define RPS3  64    /* rows per slice layer3 */
#define RPS4  16    /* rows per slice layer4 */
#define NSLS  49    /* slices per layer (both) */
#define NT3   625
#define NT4   49
#define L4O   (NB * HW3)
#define PL4O  ((size_t)NB * NSLS * HW3)

// ---------------- scratch ----------------
__device__ __half d_tT3[(size_t)NB * HWP3 * C3];
__device__ __half d_gT3[(size_t)NB * HWP3 * C3];
__device__ __half d_tT4[(size_t)NB * HWP4 * C4];
__device__ __half d_gT4[(size_t)NB * HWP4 * C4];
__device__ __half d_cd3[(size_t)NB * HW3 * HW3];
__device__ __half d_cd4[(size_t)NB * HW4 * HW4];
__device__ unsigned int d_dmin[NB * (HW3 + HW4)];
__device__ float d_pred[(size_t)NB * NSLS * (HW3 + HW4)];
__device__ float d_be[NB * (HW3 + HW4)];
__device__ float d_rm3[NB * HW3], d_rm4[NB * HW4];

// ---------------- helpers --------------------------------------------------------
__device__ __forceinline__ unsigned int fl2u(float f) {
    unsigned int u = __float_as_uint(f);
    return (u & 0x80000000u) ? ~u : (u | 0x80000000u);
}
__device__ __forceinline__ float u2fl(unsigned int u) {
    unsigned int v = (u & 0x80000000u) ? (u & 0x7FFFFFFFu) : ~u;
    return __uint_as_float(v);
}
__device__ __forceinline__ uint32_t smem_u32(const void* p) {
    uint32_t a;
    asm("{ .reg .u64 t; cvta.to.shared.u64 t, %1; cvt.u32.u64 %0, t; }" : "=r"(a) : "l"(p));
    return a;
}
__device__ __forceinline__ void cp16(uint32_t dst, const void* src) {
    asm volatile("cp.async.cg.shared.global [%0], [%1], 16;" :: "r"(dst), "l"(src));
}
#define CP_COMMIT() asm volatile("cp.async.commit_group;" ::: "memory")
#define CP_WAIT0()  asm volatile("cp.async.wait_group 0;" ::: "memory")

__device__ __forceinline__ void ldm_x4(uint32_t* r, uint32_t addr) {
    asm volatile("ldmatrix.sync.aligned.m8n8.x4.shared.b16 {%0,%1,%2,%3}, [%4];"
        : "=r"(r[0]), "=r"(r[1]), "=r"(r[2]), "=r"(r[3]) : "r"(addr));
}
__device__ __forceinline__ void mma_f16acc(uint32_t* d, const uint32_t* a, const uint32_t* b) {
    asm volatile(
        "mma.sync.aligned.m16n8k16.row.col.f16.f16.f16.f16 "
        "{%0,%1}, {%2,%3,%4,%5}, {%6,%7}, {%0,%1};"
        : "+r"(d[0]), "+r"(d[1])
        : "r"(a[0]), "r"(a[1]), "r"(a[2]), "r"(a[3]), "r"(b[0]), "r"(b[1]));
}

// ---------------- 1) fused prep --------------------------------------------------
#define SMEM_PREP 69888

__global__ __launch_bounds__(256) void prep_k(
    const float* __restrict__ g3, const float* __restrict__ t3,
    const float* __restrict__ g4, const float* __restrict__ t4,
    __half* __restrict__ tT3, __half* __restrict__ gT3,
    __half* __restrict__ tT4, __half* __restrict__ gT4,
    unsigned int* __restrict__ dmin)
{
    extern __shared__ float sm[];
    __shared__ float red[4][256];
    __shared__ float smu[32], srg[32], srt[32];

    int n  = blockIdx.y;
    int bx = blockIdx.x;
    const float *g, *t;
    __half *tT, *gT;
    int C, HW, HWpad, off, TH, sh, hw0;
    if (bx < 98) {
        g = g3; t = t3; tT = tT3; gT = gT3;
        C = C3; HW = HW3; HWpad = HWP3; off = 0; TH = 32; sh = 5; hw0 = bx * 32;
    } else {
        bx -= 98;
        g = g4; t = t4; tT = tT4; gT = gT4;
        C = C4; HW = HW4; HWpad = HWP4; off = L4O; TH = 16; sh = 4; hw0 = bx * 16;
    }
    const int PADW = TH + 1;
    float* sgm = sm;
    float* stm = sm + C * PADW;
    const int tid = threadIdx.x;
    const size_t ib = (size_t)n * C * HW;

    for (int e = tid; e < (C << sh); e += 256) {
        int c   = e >> sh;
        int hwi = e & (TH - 1);
        int hw  = hw0 + hwi;
        sgm[c * PADW + hwi] = g[ib + (size_t)c * HW + hw];
        stm[c * PADW + hwi] = t[ib + (size_t)c * HW + hw];
    }
    __syncthreads();

    const int ngrp = 256 / TH;
    const int hwi  = tid & (TH - 1);
    const int grp  = tid >> sh;
    float st = 0, st2 = 0, sg_ = 0, sg2 = 0;
    for (int c = grp; c < C; c += ngrp) {
        float tv = stm[c * PADW + hwi], gv = sgm[c * PADW + hwi];
        st += tv; st2 += tv * tv; sg_ += gv; sg2 += gv * gv;
    }
    red[0][tid] = st; red[1][tid] = st2; red[2][tid] = sg_; red[3][tid] = sg2;
    __syncthreads();
    if (grp == 0) {
        st = 0; st2 = 0; sg_ = 0; sg2 = 0;
        for (int k = 0; k < ngrp; k++) {
            st  += red[0][k * TH + hwi];
            st2 += red[1][k * TH + hwi];
            sg_ += red[2][k * TH + hwi];
            sg2 += red[3][k * TH + hwi];
        }
        float mu = st / (float)C;
        smu[hwi] = mu;
        srt[hwi] = rsqrtf(st2 - (float)C * mu * mu);
        srg[hwi] = rsqrtf(sg2 - 2.f * mu * sg_ + (float)C * mu * mu);
        dmin[off + n * HW + hw0 + hwi] = 0xFFFFFFFFu;
    }
    __syncthreads();

    const int wid = tid >> 5, lane = tid & 31;
    for (int h2 = wid; h2 < TH; h2 += 8) {
        float mu = smu[h2], rgv = srg[h2], rtv = srt[h2];
        size_t ob = ((size_t)n * HWpad + hw0 + h2) * C;
        for (int c = lane; c < C; c += 32) {
            gT[ob + c] = __float2half((sgm[c * PADW + h2] - mu) * rgv);
            tT[ob + c] = __float2half((stm[c * PADW + h2] - mu) * rtv);
        }
    }
}

// ---------------- 2) fp16 mma GEMM (fp16 acc) + fused column-min -----------------
#define KCH    64
#define RSTR   144
#define ABUF   18432
#define STG    2
#define SMEMT  (STG * 2 * ABUF)

__global__ __launch_bounds__(256, 3) void gemm_cd_mma(
    const __half* __restrict__ tT3, const __half* __restrict__ gT3,
    const __half* __restrict__ tT4, const __half* __restrict__ gT4,
    __half* __restrict__ cd3, __half* __restrict__ cd4,
    unsigned int* __restrict__ dmin)
{
    extern __shared__ char dsm[];
    const int tid  = threadIdx.x;
    const int lane = tid & 31;
    const int wid  = tid >> 5;
    const int wm   = wid & 3;
    const int wn   = wid >> 2;
    const int n    = blockIdx.y;

    int t = blockIdx.x;
    const __half *A, *B;
    __half* CD;
    unsigned int* dmb;
    int C, P, Q, Mpad, tx_, ty_;
    if (t < NT3) {
        tx_ = t % 25; ty_ = t / 25; C = C3; P = HW3; Q = HW3; Mpad = HWP3;
        A = tT3; B = gT3; CD = cd3; dmb = dmin;
    } else {
        t -= NT3;
        tx_ = t % 7; ty_ = t / 7; C = C4; P = HW4; Q = HW4; Mpad = HWP4;
        A = tT4; B = gT4; CD = cd4; dmb = dmin + L4O;
    }
    const int m0 = ty_ * 128;
    const int n0 = tx_ * 128;

    const uint32_t sbase = smem_u32(dsm);
    const uint32_t sA = sbase;
    const uint32_t sB = sbase + STG * ABUF;

    const __half* An = A + ((size_t)n * Mpad + m0) * C;
    const __half* Bn = B + ((size_t)n * Mpad + n0) * C;

    const int row_ld = tid >> 3;
    const int c16    = tid & 7;

    uint32_t acc[2][8][2];
    #pragma unroll
    for (int mi = 0; mi < 2; mi++)
        #pragma unroll
        for (int ni = 0; ni < 8; ni++) {
            acc[mi][ni][0] = 0u;
            acc[mi][ni][1] = 0u;
        }

    const int nch = C >> 6;

    auto load_chunk = [&](int c, int buf) {
        const __half* Ak = An + c * KCH;
        const __half* Bk = Bn + c * KCH;
        uint32_t da = sA + buf * ABUF + row_ld * RSTR + c16 * 16;
        uint32_t db = sB + buf * ABUF + row_ld * RSTR + c16 * 16;
        #pragma unroll
        for (int i = 0; i < 4; i++) {
            int r = row_ld + i * 32;
            cp16(da + i * 32 * RSTR, Ak + (size_t)r * C + c16 * 8);
            cp16(db + i * 32 * RSTR, Bk + (size_t)r * C + c16 * 8);
        }
    };

    load_chunk(0, 0);
    CP_COMMIT();

    const uint32_t aRow  = (uint32_t)(wm * 32 + (lane & 15));
    const uint32_t aColH = (uint32_t)((lane >> 4) * 8);
    const int quad = lane >> 3, r8 = lane & 7;
    const uint32_t bRow  = (uint32_t)(wn * 64 + (quad >> 1) * 8 + r8);
    const uint32_t bColH = (uint32_t)((quad & 1) * 8);

    for (int c = 0; c < nch; c++) {
        CP_WAIT0();
        __syncthreads();
        if (c + 1 < nch) load_chunk(c + 1, (c + 1) & 1);
        CP_COMMIT();

        const int buf = c & 1;
        const uint32_t bA = sA + buf * ABUF;
        const uint32_t bB = sB + buf * ABUF;

        #pragma unroll
        for (int ks = 0; ks < 4; ks++) {
            const int k0 = ks * 16;
            uint32_t af[2][4];
            #pragma unroll
            for (int mi = 0; mi < 2; mi++)
                ldm_x4(af[mi], bA + (aRow + mi * 16) * RSTR + (k0 + aColH) * 2);
            #pragma unroll
            for (int nbp = 0; nbp < 2; nbp++) {
                uint32_t bfr[2][4];
                #pragma unroll
                for (int j = 0; j < 2; j++)
                    ldm_x4(bfr[j], bB + (bRow + (nbp * 2 + j) * 16) * RSTR + (k0 + bColH) * 2);
                #pragma unroll
                for (int mi = 0; mi < 2; mi++) {
                    #pragma unroll
                    for (int j = 0; j < 2; j++) {
                        int nb = nbp * 2 + j;
                        mma_f16acc(acc[mi][nb * 2],     af[mi], &bfr[j][0]);
                        mma_f16acc(acc[mi][nb * 2 + 1], af[mi], &bfr[j][2]);
                    }
                }
            }
        }
    }

    // ---- epilogue ----
    const int gid = lane >> 2, t4 = lane & 3;
    const __half2 mh = __float2half2_rn(-0.5f);
    const __half2 ph = __float2half2_rn(0.5f);
    __half2 cmin2[8];
    #pragma unroll
    for (int i = 0; i < 8; i++) cmin2[i] = __float2half2_rn(60000.f);

    __half* Cn = CD + (size_t)n * P * Q;
    #pragma unroll
    for (int mi = 0; mi < 2; mi++) {
        #pragma unroll
        for (int h = 0; h < 2; h++) {
            int r = m0 + wm * 32 + mi * 16 + h * 8 + gid;
            if (r < P) {
                __half* rp = Cn + (size_t)r * Q;
                #pragma unroll
                for (int ni = 0; ni < 8; ni++) {
                    int col = n0 + wn * 64 + ni * 8 + t4 * 2;
                    __half2 a = *(__half2*)&acc[mi][ni][h];
                    __half2 cdv = __hfma2(a, mh, ph);
                    cmin2[ni] = __hmin2(cmin2[ni], cdv);
                    if (col < Q)
                        *(__half2*)(rp + col) = cdv;
                }
            }
        }
    }
    #pragma unroll
    for (int o = 4; o < 32; o <<= 1)
        #pragma unroll
        for (int i = 0; i < 8; i++) {
            uint32_t v = __shfl_xor_sync(0xffffffffu, *(uint32_t*)&cmin2[i], o);
            cmin2[i] = __hmin2(cmin2[i], *(__half2*)&v);
        }

    __syncthreads();
    float* smin = (float*)dsm;
    if (gid == 0) {
        #pragma unroll
        for (int ni = 0; ni < 8; ni++) {
            float2 f = __half22float2(cmin2[ni]);
            smin[wm * 128 + wn * 64 + ni * 8 + t4 * 2]     = f.x;
            smin[wm * 128 + wn * 64 + ni * 8 + t4 * 2 + 1] = f.y;
        }
    }
    __syncthreads();
    if (tid < 128) {
        int colg = n0 + tid;
        if (colg < Q) {
            float m = fminf(fminf(smin[tid], smin[128 + tid]),
                            fminf(smin[256 + tid], smin[384 + tid]));
            atomicMin(&dmb[n * Q + colg], fl2u(m));
        }
    }
}

// ---------------- 3) partial column sum of exp2 (half2 inner, fp32 outer) --------
__global__ __launch_bounds__(256) void colsum_k(
    const __half* __restrict__ cd3, const __half* __restrict__ cd4,
    const unsigned int* __restrict__ dmin, float* __restrict__ pred)
{
    int n = blockIdx.z;
    int y = blockIdx.y;
    const __half* cd;
    const unsigned int* dmb;
    float* pout;
    int P, Q, sl, rps;
    if (y < NSLS) { cd = cd3; dmb = dmin; pout = pred; P = HW3; Q = HW3; sl = y; rps = RPS3; }
    else { cd = cd4; dmb = dmin + L4O; pout = pred + PL4O; P = HW4; Q = HW4; sl = y - NSLS; rps = RPS4; }
    int nq8 = Q >> 3;
    int q8 = blockIdx.x * 256 + threadIdx.x;
    if (q8 >= nq8) return;
    const uint4* base = (const uint4*)(cd + (size_t)n * P * Q) + q8;

    __half2 ce2[4];
    {
        uint4 u0 = *(const uint4*)(dmb + n * Q + q8 * 8);
        uint4 u1 = *(const uint4*)(dmb + n * Q + q8 * 8 + 4);
        float c0 = fmaxf((-2.0f * LOG2E) / (u2fl(u0.x) + EPSV), -60000.f);
        float c1 = fmaxf((-2.0f * LOG2E) / (u2fl(u0.y) + EPSV), -60000.f);
        float c2 = fmaxf((-2.0f * LOG2E) / (u2fl(u0.z) + EPSV), -60000.f);
        float c3 = fmaxf((-2.0f * LOG2E) / (u2fl(u0.w) + EPSV), -60000.f);
        float c4 = fmaxf((-2.0f * LOG2E) / (u2fl(u1.x) + EPSV), -60000.f);
        float c5 = fmaxf((-2.0f * LOG2E) / (u2fl(u1.y) + EPSV), -60000.f);
        float c6 = fmaxf((-2.0f * LOG2E) / (u2fl(u1.z) + EPSV), -60000.f);
        float c7 = fmaxf((-2.0f * LOG2E) / (u2fl(u1.w) + EPSV), -60000.f);
        ce2[0] = __floats2half2_rn(c0, c1);
        ce2[1] = __floats2half2_rn(c2, c3);
        ce2[2] = __floats2half2_rn(c4, c5);
        ce2[3] = __floats2half2_rn(c6, c7);
    }
    const __half2 k2c2 = __float2half2_rn(K2C);
    float2 fs0 = make_float2(0.f, 0.f), fs1 = fs0, fs2 = fs0, fs3 = fs0;

    int r0 = sl * rps;
    for (int rc = 0; rc < rps; rc += 16) {
        __half2 a0 = __float2half2_rn(0.f), a1 = a0, a2 = a0, a3 = a0;
        #pragma unroll 4
        for (int r = r0 + rc; r < r0 + rc + 16; r++) {
            uint4 v = base[(size_t)r * nq8];
            a0 = __hadd2(a0, h2exp2(__hfma2(ce2[0], *(__half2*)&v.x, k2c2)));
            a1 = __hadd2(a1, h2exp2(__hfma2(ce2[1], *(__half2*)&v.y, k2c2)));
            a2 = __hadd2(a2, h2exp2(__hfma2(ce2[2], *(__half2*)&v.z, k2c2)));
            a3 = __hadd2(a3, h2exp2(__hfma2(ce2[3], *(__half2*)&v.w, k2c2)));
        }
        float2 f;
        f = __half22float2(a0); fs0.x += f.x; fs0.y += f.y;
        f = __half22float2(a1); fs1.x += f.x; fs1.y += f.y;
        f = __half22float2(a2); fs2.x += f.x; fs2.y += f.y;
        f = __half22float2(a3); fs3.x += f.x; fs3.y += f.y;
    }
    float* pw = pout + ((size_t)n * NSLS + sl) * Q + q8 * 8;
    *(float4*)pw       = make_float4(fs0.x, fs0.y, fs1.x, fs1.y);
    *(float4*)(pw + 4) = make_float4(fs2.x, fs2.y, fs3.x, fs3.y);
}

// ---------------- 4) stage2 sum -> be = 2log2e - log2(S) -------------------------
__global__ __launch_bounds__(256) void stage2_sum_k(
    const float* __restrict__ pred, float* __restrict__ be)
{
    int n = blockIdx.y;
    int bx = blockIdx.x;
    const float* pin;
    float* bo;
    int Q, q;
    if (bx < 13) { pin = pred; bo = be; Q = HW3; q = bx * 256 + threadIdx.x; }
    else { pin = pred + PL4O; bo = be + L4O; Q = HW4; q = (bx - 13) * 256 + threadIdx.x; }
    if (q >= Q) return;
    float s = 0.f;
    #pragma unroll 7
    for (int sl = 0; sl < NSLS; sl++)
        s += pin[((size_t)n * NSLS + sl) * Q + q];
    bo[n * Q + q] = K2C - log2f(s);
}

// ---------------- 5) row max (half2, both layers) --------------------------------
__global__ __launch_bounds__(256) void rowmax_k(
    const __half* __restrict__ cd3, const __half* __restrict__ cd4,
    const unsigned int* __restrict__ dmin, const float* __restrict__ be,
    float* __restrict__ rm3, float* __restrict__ rm4)
{
    __shared__ __half2 sc2[HW3 / 2], sb2[HW3 / 2];
    int n = blockIdx.y;
    int bx = blockIdx.x;
    const __half* cd;
    const unsigned int* dmb;
    const float* beb;
    float* rm;
    int P, Q, pb;
    if (bx < 392) { cd = cd3; dmb = dmin; beb = be; rm = rm3; P = HW3; Q = HW3; pb = bx; }
    else { cd = cd4; dmb = dmin + L4O; beb = be + L4O; rm = rm4; P = HW4; Q = HW4; pb = bx - 392; }
    int Qh = Q >> 1;
    for (int i = threadIdx.x; i < Qh; i += 256) {
        float c0 = fmaxf((-2.0f * LOG2E) / (u2fl(dmb[n * Q + 2 * i]) + EPSV), -60000.f);
        float c1 = fmaxf((-2.0f * LOG2E) / (u2fl(dmb[n * Q + 2 * i + 1]) + EPSV), -60000.f);
        sc2[i] = __floats2half2_rn(c0, c1);
        sb2[i] = __floats2half2_rn(beb[n * Q + 2 * i], beb[n * Q + 2 * i + 1]);
    }
    __syncthreads();
    int p = pb * 8 + (threadIdx.x >> 5);
    int lane = threadIdx.x & 31;
    if (p >= P) return;
    const uint4* row = (const uint4*)(cd + (size_t)n * P * Q + (size_t)p * Q);
    int nq8 = Q >> 3;
    __half2 m2 = __float2half2_rn(-60000.f);
    for (int i = lane; i < nq8; i += 32) {
        uint4 v = row[i];
        int qh = i * 4;
        m2 = __hmax2(m2, __hfma2(sc2[qh],     *(__half2*)&v.x, sb2[qh]));
        m2 = __hmax2(m2, __hfma2(sc2[qh + 1], *(__half2*)&v.y, sb2[qh + 1]));
        m2 = __hmax2(m2, __hfma2(sc2[qh + 2], *(__half2*)&v.z, sb2[qh + 2]));
        m2 = __hmax2(m2, __hfma2(sc2[qh + 3], *(__half2*)&v.w, sb2[qh + 3]));
    }
    float2 fm = __half22float2(m2);
    float m = fmaxf(fm.x, fm.y);
    #pragma unroll
    for (int o = 16; o > 0; o >>= 1)
        m = fmaxf(m, __shfl_xor_sync(0xffffffffu, m, o));
    if (lane == 0) rm[n * P + p] = m;
}

// ---------------- 6) final -------------------------------------------------------
__global__ __launch_bounds__(256) void final_k(
    const float* __restrict__ rm3, const float* __restrict__ rm4,
    float* __restrict__ out)
{
    __shared__ float red[256];
    int tid = threadIdx.x;
    float total = 0.f;
    for (int n = 0; n < NB; n++) {
        float s = 0.f;
        for (int p = tid; p < HW3; p += 256) s += exp2f(rm3[n * HW3 + p]);
        red[tid] = s;
        __syncthreads();
        for (int o = 128; o > 0; o >>= 1) {
            if (tid < o) red[tid] += red[tid + o];
            __syncthreads();
        }
        total += 0.5f * (-logf(red[0] / (float)HW3));
        __syncthreads();
    }
    for (int n = 0; n < NB; n++) {
        float s = 0.f;
        for (int p = tid; p < HW4; p += 256) s += exp2f(rm4[n * HW4 + p]);
        red[tid] = s;
        __syncthreads();
        for (int o = 128; o > 0; o >>= 1) {
            if (tid < o) red[tid] += red[tid + o];
            __syncthreads();
        }
        total += 1.0f * (-logf(red[0] / (float)HW4));
        __syncthreads();
    }
    if (tid == 0) out[0] = total;
}

// ---------------- launch ---------------------------------------------------------
extern "C" void kernel_launch(void* const* d_in, const int* in_sizes, int n_in,
                              void* d_out, int out_size)
{
    const float* gen3 = (const float*)d_in[0];
    const float* tar3 = (const float*)d_in[1];
    const float* gen4 = (const float*)d_in[2];
    const float* tar4 = (const float*)d_in[3];

    __half *tT3, *gT3, *tT4, *gT4;
    __half *cd3, *cd4;
    float *pred, *be, *rm3, *rm4;
    unsigned int* dmin;
    cudaGetSymbolAddress((void**)&tT3, d_tT3);
    cudaGetSymbolAddress((void**)&gT3, d_gT3);
    cudaGetSymbolAddress((void**)&tT4, d_tT4);
    cudaGetSymbolAddress((void**)&gT4, d_gT4);
    cudaGetSymbolAddress((void**)&cd3, d_cd3);
    cudaGetSymbolAddress((void**)&cd4, d_cd4);
    cudaGetSymbolAddress((void**)&dmin, d_dmin);
    cudaGetSymbolAddress((void**)&pred, d_pred);
    cudaGetSymbolAddress((void**)&be, d_be);
    cudaGetSymbolAddress((void**)&rm3, d_rm3);
    cudaGetSymbolAddress((void**)&rm4, d_rm4);

    cudaFuncSetAttribute(prep_k, cudaFuncAttributeMaxDynamicSharedMemorySize, SMEM_PREP);
    cudaFuncSetAttribute(gemm_cd_mma, cudaFuncAttributeMaxDynamicSharedMemorySize, SMEMT);

    prep_k<<<dim3(98 + 49, NB), 256, SMEM_PREP>>>(gen3, tar3, gen4, tar4,
                                                  tT3, gT3, tT4, gT4, dmin);
    gemm_cd_mma<<<dim3(NT3 + NT4, NB), 256, SMEMT>>>(tT3, gT3, tT4, gT4, cd3, cd4, dmin);
    colsum_k<<<dim3(2, NSLS * 2, NB), 256>>>(cd3, cd4, dmin, pred);
    stage2_sum_k<<<dim3(13 + 4, NB), 256>>>(pred, be);
    rowmax_k<<<dim3(392 + 98, NB), 256>>>(cd3, cd4, dmin, be, rm3, rm4);
    final_k<<<1, 256>>>(rm3, rm4, (float*)d_out);
}

// round 17
// speedup vs baseline: 1.0395x; 1.0395x over previous
#include <cuda_runtime.h>
#include <cuda_fp16.h>
#include <math.h>
#include <stdint.h>

#define NB   4
#define C3   256
#define HW3  3136
#define HWP3 3200
#define C4   512
#define HW4  784
#define HWP4 896
#define EPSV 1e-5f
#define LOG2E 1.4426950408889634f
#define K2C   2.8853900817779268f   /* 2*log2(e) */

#define RPSS  16
#define NSLS3 196
#define NSLS4 49
#define NT3   625
#define NT4   49
#define L4O   (NB * HW3)
#define PL4O  ((size_t)NB * NSLS3 * HW3)

// ---------------- scratch ----------------
__device__ __half d_tT3[(size_t)NB * HWP3 * C3];
__device__ __half d_gT3[(size_t)NB * HWP3 * C3];
__device__ __half d_tT4[(size_t)NB * HWP4 * C4];
__device__ __half d_gT4[(size_t)NB * HWP4 * C4];
__device__ __half d_cd3[(size_t)NB * HW3 * HW3];
__device__ __half d_cd4[(size_t)NB * HW4 * HW4];
__device__ unsigned int d_dmin[NB * (HW3 + HW4)];
__device__ float d_pred[(size_t)NB * (NSLS3 * HW3 + NSLS4 * HW4)];
__device__ float d_be[NB * (HW3 + HW4)];
__device__ float d_rm3[NB * HW3], d_rm4[NB * HW4];

// ---------------- helpers --------------------------------------------------------
__device__ __forceinline__ unsigned int fl2u(float f) {
    unsigned int u = __float_as_uint(f);
    return (u & 0x80000000u) ? ~u : (u | 0x80000000u);
}
__device__ __forceinline__ float u2fl(unsigned int u) {
    unsigned int v = (u & 0x80000000u) ? (u & 0x7FFFFFFFu) : ~u;
    return __uint_as_float(v);
}
__device__ __forceinline__ uint32_t smem_u32(const void* p) {
    uint32_t a;
    asm("{ .reg .u64 t; cvta.to.shared.u64 t, %1; cvt.u32.u64 %0, t; }" : "=r"(a) : "l"(p));
    return a;
}
__device__ __forceinline__ void cp16(uint32_t dst, const void* src) {
    asm volatile("cp.async.cg.shared.global [%0], [%1], 16;" :: "r"(dst), "l"(src));
}
#define CP_COMMIT() asm volatile("cp.async.commit_group;" ::: "memory")
#define CP_WAIT0()  asm volatile("cp.async.wait_group 0;" ::: "memory")

__device__ __forceinline__ void ldm_x4(uint32_t* r, uint32_t addr) {
    asm volatile("ldmatrix.sync.aligned.m8n8.x4.shared.b16 {%0,%1,%2,%3}, [%4];"
        : "=r"(r[0]), "=r"(r[1]), "=r"(r[2]), "=r"(r[3]) : "r"(addr));
}
__device__ __forceinline__ void mma_f16acc(uint32_t* d, const uint32_t* a, const uint32_t* b) {
    asm volatile(
        "mma.sync.aligned.m16n8k16.row.col.f16.f16.f16.f16 "
        "{%0,%1}, {%2,%3,%4,%5}, {%6,%7}, {%0,%1};"
        : "+r"(d[0]), "+r"(d[1])
        : "r"(a[0]), "r"(a[1]), "r"(a[2]), "r"(a[3]), "r"(b[0]), "r"(b[1]));
}

// ---------------- 1) fused prep --------------------------------------------------
#define SMEM_PREP 69888

__global__ __launch_bounds__(256) void prep_k(
    const float* __restrict__ g3, const float* __restrict__ t3,
    const float* __restrict__ g4, const float* __restrict__ t4,
    __half* __restrict__ tT3, __half* __restrict__ gT3,
    __half* __restrict__ tT4, __half* __restrict__ gT4,
    unsigned int* __restrict__ dmin)
{
    extern __shared__ float sm[];
    __shared__ float red[4][256];
    __shared__ float smu[32], srg[32], srt[32];

    int n  = blockIdx.y;
    int bx = blockIdx.x;
    const float *g, *t;
    __half *tT, *gT;
    int C, HW, HWpad, off, TH, sh, hw0;
    if (bx < 98) {
        g = g3; t = t3; tT = tT3; gT = gT3;
        C = C3; HW = HW3; HWpad = HWP3; off = 0; TH = 32; sh = 5; hw0 = bx * 32;
    } else {
        bx -= 98;
        g = g4; t = t4; tT = tT4; gT = gT4;
        C = C4; HW = HW4; HWpad = HWP4; off = L4O; TH = 16; sh = 4; hw0 = bx * 16;
    }
    const int PADW = TH + 1;
    float* sgm = sm;
    float* stm = sm + C * PADW;
    const int tid = threadIdx.x;
    const size_t ib = (size_t)n * C * HW;

    for (int e = tid; e < (C << sh); e += 256) {
        int c   = e >> sh;
        int hwi = e & (TH - 1);
        int hw  = hw0 + hwi;
        sgm[c * PADW + hwi] = g[ib + (size_t)c * HW + hw];
        stm[c * PADW + hwi] = t[ib + (size_t)c * HW + hw];
    }
    __syncthreads();

    const int ngrp = 256 / TH;
    const int hwi  = tid & (TH - 1);
    const int grp  = tid >> sh;
    float st = 0, st2 = 0, sg_ = 0, sg2 = 0;
    for (int c = grp; c < C; c += ngrp) {
        float tv = stm[c * PADW + hwi], gv = sgm[c * PADW + hwi];
        st += tv; st2 += tv * tv; sg_ += gv; sg2 += gv * gv;
    }
    red[0][tid] = st; red[1][tid] = st2; red[2][tid] = sg_; red[3][tid] = sg2;
    __syncthreads();
    if (grp == 0) {
        st = 0; st2 = 0; sg_ = 0; sg2 = 0;
        for (int k = 0; k < ngrp; k++) {
            st  += red[0][k * TH + hwi];
            st2 += red[1][k * TH + hwi];
            sg_ += red[2][k * TH + hwi];
            sg2 += red[3][k * TH + hwi];
        }
        float mu = st / (float)C;
        smu[hwi] = mu;
        srt[hwi] = rsqrtf(st2 - (float)C * mu * mu);
        srg[hwi] = rsqrtf(sg2 - 2.f * mu * sg_ + (float)C * mu * mu);
        dmin[off + n * HW + hw0 + hwi] = 0xFFFFFFFFu;
    }
    __syncthreads();

    const int wid = tid >> 5, lane = tid & 31;
    for (int h2 = wid; h2 < TH; h2 += 8) {
        float mu = smu[h2], rgv = srg[h2], rtv = srt[h2];
        size_t ob = ((size_t)n * HWpad + hw0 + h2) * C;
        for (int c = lane; c < C; c += 32) {
            gT[ob + c] = __float2half((sgm[c * PADW + h2] - mu) * rgv);
            tT[ob + c] = __float2half((stm[c * PADW + h2] - mu) * rtv);
        }
    }
}

// ---------------- 2) fp16 mma GEMM (fp16 acc) + fused column-min -----------------
#define KCH    64
#define RSTR   144
#define ABUF   18432
#define STG    2
#define SMEMT  (STG * 2 * ABUF)

__global__ __launch_bounds__(256, 3) void gemm_cd_mma(
    const __half* __restrict__ tT3, const __half* __restrict__ gT3,
    const __half* __restrict__ tT4, const __half* __restrict__ gT4,
    __half* __restrict__ cd3, __half* __restrict__ cd4,
    unsigned int* __restrict__ dmin)
{
    extern __shared__ char dsm[];
    const int tid  = threadIdx.x;
    const int lane = tid & 31;
    const int wid  = tid >> 5;
    const int wm   = wid & 3;
    const int wn   = wid >> 2;
    const int n    = blockIdx.y;

    int t = blockIdx.x;
    const __half *A, *B;
    __half* CD;
    unsigned int* dmb;
    int C, P, Q, Mpad, tx_, ty_;
    if (t < NT3) {
        tx_ = t % 25; ty_ = t / 25; C = C3; P = HW3; Q = HW3; Mpad = HWP3;
        A = tT3; B = gT3; CD = cd3; dmb = dmin;
    } else {
        t -= NT3;
        tx_ = t % 7; ty_ = t / 7; C = C4; P = HW4; Q = HW4; Mpad = HWP4;
        A = tT4; B = gT4; CD = cd4; dmb = dmin + L4O;
    }
    const int m0 = ty_ * 128;
    const int n0 = tx_ * 128;

    const uint32_t sbase = smem_u32(dsm);
    const uint32_t sA = sbase;
    const uint32_t sB = sbase + STG * ABUF;

    const __half* An = A + ((size_t)n * Mpad + m0) * C;
    const __half* Bn = B + ((size_t)n * Mpad + n0) * C;

    const int row_ld = tid >> 3;
    const int c16    = tid & 7;

    uint32_t acc[2][8][2];
    #pragma unroll
    for (int mi = 0; mi < 2; mi++)
        #pragma unroll
        for (int ni = 0; ni < 8; ni++) {
            acc[mi][ni][0] = 0u;
            acc[mi][ni][1] = 0u;
        }

    const int nch = C >> 6;

    auto load_chunk = [&](int c, int buf) {
        const __half* Ak = An + c * KCH;
        const __half* Bk = Bn + c * KCH;
        uint32_t da = sA + buf * ABUF + row_ld * RSTR + c16 * 16;
        uint32_t db = sB + buf * ABUF + row_ld * RSTR + c16 * 16;
        #pragma unroll
        for (int i = 0; i < 4; i++) {
            int r = row_ld + i * 32;
            cp16(da + i * 32 * RSTR, Ak + (size_t)r * C + c16 * 8);
            cp16(db + i * 32 * RSTR, Bk + (size_t)r * C + c16 * 8);
        }
    };

    load_chunk(0, 0);
    CP_COMMIT();

    const uint32_t aRow  = (uint32_t)(wm * 32 + (lane & 15));
    const uint32_t aColH = (uint32_t)((lane >> 4) * 8);
    const int quad = lane >> 3, r8 = lane & 7;
    const uint32_t bRow  = (uint32_t)(wn * 64 + (quad >> 1) * 8 + r8);
    const uint32_t bColH = (uint32_t)((quad & 1) * 8);

    for (int c = 0; c < nch; c++) {
        CP_WAIT0();
        __syncthreads();
        if (c + 1 < nch) load_chunk(c + 1, (c + 1) & 1);
        CP_COMMIT();

        const int buf = c & 1;
        const uint32_t bA = sA + buf * ABUF;
        const uint32_t bB = sB + buf * ABUF;

        #pragma unroll
        for (int ks = 0; ks < 4; ks++) {
            const int k0 = ks * 16;
            uint32_t af[2][4];
            #pragma unroll
            for (int mi = 0; mi < 2; mi++)
                ldm_x4(af[mi], bA + (aRow + mi * 16) * RSTR + (k0 + aColH) * 2);
            #pragma unroll
            for (int nbp = 0; nbp < 2; nbp++) {
                uint32_t bfr[2][4];
                #pragma unroll
                for (int j = 0; j < 2; j++)
                    ldm_x4(bfr[j], bB + (bRow + (nbp * 2 + j) * 16) * RSTR + (k0 + bColH) * 2);
                #pragma unroll
                for (int mi = 0; mi < 2; mi++) {
                    #pragma unroll
                    for (int j = 0; j < 2; j++) {
                        int nb = nbp * 2 + j;
                        mma_f16acc(acc[mi][nb * 2],     af[mi], &bfr[j][0]);
                        mma_f16acc(acc[mi][nb * 2 + 1], af[mi], &bfr[j][2]);
                    }
                }
            }
        }
    }

    // ---- epilogue ----
    const int gid = lane >> 2, t4 = lane & 3;
    const __half2 mh = __float2half2_rn(-0.5f);
    const __half2 ph = __float2half2_rn(0.5f);
    __half2 cmin2[8];
    #pragma unroll
    for (int i = 0; i < 8; i++) cmin2[i] = __float2half2_rn(60000.f);

    __half* Cn = CD + (size_t)n * P * Q;
    #pragma unroll
    for (int mi = 0; mi < 2; mi++) {
        #pragma unroll
        for (int h = 0; h < 2; h++) {
            int r = m0 + wm * 32 + mi * 16 + h * 8 + gid;
            if (r < P) {
                __half* rp = Cn + (size_t)r * Q;
                #pragma unroll
                for (int ni = 0; ni < 8; ni++) {
                    int col = n0 + wn * 64 + ni * 8 + t4 * 2;
                    __half2 a = *(__half2*)&acc[mi][ni][h];
                    __half2 cdv = __hfma2(a, mh, ph);
                    cmin2[ni] = __hmin2(cmin2[ni], cdv);
                    if (col < Q)
                        *(__half2*)(rp + col) = cdv;
                }
            }
        }
    }
    #pragma unroll
    for (int o = 4; o < 32; o <<= 1)
        #pragma unroll
        for (int i = 0; i < 8; i++) {
            uint32_t v = __shfl_xor_sync(0xffffffffu, *(uint32_t*)&cmin2[i], o);
            cmin2[i] = __hmin2(cmin2[i], *(__half2*)&v);
        }

    __syncthreads();
    float* smin = (float*)dsm;
    if (gid == 0) {
        #pragma unroll
        for (int ni = 0; ni < 8; ni++) {
            float2 f = __half22float2(cmin2[ni]);
            smin[wm * 128 + wn * 64 + ni * 8 + t4 * 2]     = f.x;
            smin[wm * 128 + wn * 64 + ni * 8 + t4 * 2 + 1] = f.y;
        }
    }
    __syncthreads();
    if (tid < 128) {
        int colg = n0 + tid;
        if (colg < Q) {
            float m = fminf(fminf(smin[tid], smin[128 + tid]),
                            fminf(smin[256 + tid], smin[384 + tid]));
            atomicMin(&dmb[n * Q + colg], fl2u(m));
        }
    }
}

// ---------------- 3) partial column sum of exp2 (half2, both layers) -------------
__global__ __launch_bounds__(256) void colsum_k(
    const __half* __restrict__ cd3, const __half* __restrict__ cd4,
    const unsigned int* __restrict__ dmin, float* __restrict__ pred)
{
    int n = blockIdx.z;
    int y = blockIdx.y;
    const __half* cd;
    const unsigned int* dmb;
    float* pout;
    int P, Q, sl, nsl;
    if (y < NSLS3) { cd = cd3; dmb = dmin; pout = pred; P = HW3; Q = HW3; sl = y; nsl = NSLS3; }
    else { cd = cd4; dmb = dmin + L4O; pout = pred + PL4O; P = HW4; Q = HW4; sl = y - NSLS3; nsl = NSLS4; }
    int nq8 = Q >> 3;
    int q8 = blockIdx.x * 256 + threadIdx.x;
    if (q8 >= nq8) return;
    const uint4* base = (const uint4*)(cd + (size_t)n * P * Q) + q8;

    __half2 ce2[4];
    {
        uint4 u0 = *(const uint4*)(dmb + n * Q + q8 * 8);
        uint4 u1 = *(const uint4*)(dmb + n * Q + q8 * 8 + 4);
        float c0 = fmaxf((-2.0f * LOG2E) / (u2fl(u0.x) + EPSV), -60000.f);
        float c1 = fmaxf((-2.0f * LOG2E) / (u2fl(u0.y) + EPSV), -60000.f);
        float c2 = fmaxf((-2.0f * LOG2E) / (u2fl(u0.z) + EPSV), -60000.f);
        float c3 = fmaxf((-2.0f * LOG2E) / (u2fl(u0.w) + EPSV), -60000.f);
        float c4 = fmaxf((-2.0f * LOG2E) / (u2fl(u1.x) + EPSV), -60000.f);
        float c5 = fmaxf((-2.0f * LOG2E) / (u2fl(u1.y) + EPSV), -60000.f);
        float c6 = fmaxf((-2.0f * LOG2E) / (u2fl(u1.z) + EPSV), -60000.f);
        float c7 = fmaxf((-2.0f * LOG2E) / (u2fl(u1.w) + EPSV), -60000.f);
        ce2[0] = __floats2half2_rn(c0, c1);
        ce2[1] = __floats2half2_rn(c2, c3);
        ce2[2] = __floats2half2_rn(c4, c5);
        ce2[3] = __floats2half2_rn(c6, c7);
    }
    const __half2 k2c2 = __float2half2_rn(K2C);
    __half2 a0 = __float2half2_rn(0.f), a1 = a0, a2 = a0, a3 = a0;

    int r0 = sl * RPSS;
    #pragma unroll 4
    for (int r = r0; r < r0 + RPSS; r++) {
        uint4 v = base[(size_t)r * nq8];
        a0 = __hadd2(a0, h2exp2(__hfma2(ce2[0], *(__half2*)&v.x, k2c2)));
        a1 = __hadd2(a1, h2exp2(__hfma2(ce2[1], *(__half2*)&v.y, k2c2)));
        a2 = __hadd2(a2, h2exp2(__hfma2(ce2[2], *(__half2*)&v.z, k2c2)));
        a3 = __hadd2(a3, h2exp2(__hfma2(ce2[3], *(__half2*)&v.w, k2c2)));
    }
    float2 f0 = __half22float2(a0), f1 = __half22float2(a1);
    float2 f2 = __half22float2(a2), f3 = __half22float2(a3);
    float* pw = pout + ((size_t)n * nsl + sl) * Q + q8 * 8;
    *(float4*)pw       = make_float4(f0.x, f0.y, f1.x, f1.y);
    *(float4*)(pw + 4) = make_float4(f2.x, f2.y, f3.x, f3.y);
}

// ---------------- 4) stage2 sum (parallel over slice groups) ---------------------
// block = 64 q-lanes x 4 slice-groups; each thread sums nsl/4 slices.
__global__ __launch_bounds__(256) void stage2_sum_k(
    const float* __restrict__ pred, float* __restrict__ be)
{
    __shared__ float red[4][64];
    int n = blockIdx.y;
    int bx = blockIdx.x;
    const float* pin;
    float* bo;
    int Q, nsl, qb;
    if (bx < 49) { pin = pred; bo = be; Q = HW3; nsl = NSLS3; qb = bx * 64; }
    else { pin = pred + PL4O; bo = be + L4O; Q = HW4; nsl = NSLS4; qb = (bx - 49) * 64; }
    int qg  = threadIdx.x & 63;
    int grp = threadIdx.x >> 6;
    int q   = qb + qg;
    float s = 0.f;
    if (q < Q) {
        for (int sl = grp; sl < nsl; sl += 4)
            s += pin[((size_t)n * nsl + sl) * Q + q];
    }
    red[grp][qg] = s;
    __syncthreads();
    if (grp == 0 && q < Q) {
        float S = red[0][qg] + red[1][qg] + red[2][qg] + red[3][qg];
        bo[n * Q + q] = K2C - log2f(S);
    }
}

// ---------------- 5) row max (half2, both layers) --------------------------------
__global__ __launch_bounds__(256) void rowmax_k(
    const __half* __restrict__ cd3, const __half* __restrict__ cd4,
    const unsigned int* __restrict__ dmin, const float* __restrict__ be,
    float* __restrict__ rm3, float* __restrict__ rm4)
{
    __shared__ __half2 sc2[HW3 / 2], sb2[HW3 / 2];
    int n = blockIdx.y;
    int bx = blockIdx.x;
    const __half* cd;
    const unsigned int* dmb;
    const float* beb;
    float* rm;
    int P, Q, pb;
    if (bx < 392) { cd = cd3; dmb = dmin; beb = be; rm = rm3; P = HW3; Q = HW3; pb = bx; }
    else { cd = cd4; dmb = dmin + L4O; beb = be + L4O; rm = rm4; P = HW4; Q = HW4; pb = bx - 392; }
    int Qh = Q >> 1;
    for (int i = threadIdx.x; i < Qh; i += 256) {
        float c0 = fmaxf((-2.0f * LOG2E) / (u2fl(dmb[n * Q + 2 * i]) + EPSV), -60000.f);
        float c1 = fmaxf((-2.0f * LOG2E) / (u2fl(dmb[n * Q + 2 * i + 1]) + EPSV), -60000.f);
        sc2[i] = __floats2half2_rn(c0, c1);
        sb2[i] = __floats2half2_rn(beb[n * Q + 2 * i], beb[n * Q + 2 * i + 1]);
    }
    __syncthreads();
    int p = pb * 8 + (threadIdx.x >> 5);
    int lane = threadIdx.x & 31;
    if (p >= P) return;
    const uint4* row = (const uint4*)(cd + (size_t)n * P * Q + (size_t)p * Q);
    int nq8 = Q >> 3;
    __half2 m2 = __float2half2_rn(-60000.f);
    for (int i = lane; i < nq8; i += 32) {
        uint4 v = row[i];
        int qh = i * 4;
        m2 = __hmax2(m2, __hfma2(sc2[qh],     *(__half2*)&v.x, sb2[qh]));
        m2 = __hmax2(m2, __hfma2(sc2[qh + 1], *(__half2*)&v.y, sb2[qh + 1]));
        m2 = __hmax2(m2, __hfma2(sc2[qh + 2], *(__half2*)&v.z, sb2[qh + 2]));
        m2 = __hmax2(m2, __hfma2(sc2[qh + 3], *(__half2*)&v.w, sb2[qh + 3]));
    }
    float2 fm = __half22float2(m2);
    float m = fmaxf(fm.x, fm.y);
    #pragma unroll
    for (int o = 16; o > 0; o >>= 1)
        m = fmaxf(m, __shfl_xor_sync(0xffffffffu, m, o));
    if (lane == 0) rm[n * P + p] = m;
}

// ---------------- 6) final -------------------------------------------------------
__global__ __launch_bounds__(256) void final_k(
    const float* __restrict__ rm3, const float* __restrict__ rm4,
    float* __restrict__ out)
{
    __shared__ float red[256];
    int tid = threadIdx.x;
    float total = 0.f;
    for (int n = 0; n < NB; n++) {
        float s = 0.f;
        for (int p = tid; p < HW3; p += 256) s += exp2f(rm3[n * HW3 + p]);
        red[tid] = s;
        __syncthreads();
        for (int o = 128; o > 0; o >>= 1) {
            if (tid < o) red[tid] += red[tid + o];
            __syncthreads();
        }
        total += 0.5f * (-logf(red[0] / (float)HW3));
        __syncthreads();
    }
    for (int n = 0; n < NB; n++) {
        float s = 0.f;
        for (int p = tid; p < HW4; p += 256) s += exp2f(rm4[n * HW4 + p]);
        red[tid] = s;
        __syncthreads();
        for (int o = 128; o > 0; o >>= 1) {
            if (tid < o) red[tid] += red[tid + o];
            __syncthreads();
        }
        total += 1.0f * (-logf(red[0] / (float)HW4));
        __syncthreads();
    }
    if (tid == 0) out[0] = total;
}

// ---------------- launch ---------------------------------------------------------
extern "C" void kernel_launch(void* const* d_in, const int* in_sizes, int n_in,
                              void* d_out, int out_size)
{
    const float* gen3 = (const float*)d_in[0];
    const float* tar3 = (const float*)d_in[1];
    const float* gen4 = (const float*)d_in[2];
    const float* tar4 = (const float*)d_in[3];

    __half *tT3, *gT3, *tT4, *gT4;
    __half *cd3, *cd4;
    float *pred, *be, *rm3, *rm4;
    unsigned int* dmin;
    cudaGetSymbolAddress((void**)&tT3, d_tT3);
    cudaGetSymbolAddress((void**)&gT3, d_gT3);
    cudaGetSymbolAddress((void**)&tT4, d_tT4);
    cudaGetSymbolAddress((void**)&gT4, d_gT4);
    cudaGetSymbolAddress((void**)&cd3, d_cd3);
    cudaGetSymbolAddress((void**)&cd4, d_cd4);
    cudaGetSymbolAddress((void**)&dmin, d_dmin);
    cudaGetSymbolAddress((void**)&pred, d_pred);
    cudaGetSymbolAddress((void**)&be, d_be);
    cudaGetSymbolAddress((void**)&rm3, d_rm3);
    cudaGetSymbolAddress((void**)&rm4, d_rm4);

    cudaFuncSetAttribute(prep_k, cudaFuncAttributeMaxDynamicSharedMemorySize, SMEM_PREP);
    cudaFuncSetAttribute(gemm_cd_mma, cudaFuncAttributeMaxDynamicSharedMemorySize, SMEMT);

    prep_k<<<dim3(98 + 49, NB), 256, SMEM_PREP>>>(gen3, tar3, gen4, tar4,
                                                  tT3, gT3, tT4, gT4, dmin);
    gemm_cd_mma<<<dim3(NT3 + NT4, NB), 256, SMEMT>>>(tT3, gT3, tT4, gT4, cd3, cd4, dmin);
    colsum_k<<<dim3(2, NSLS3 + NSLS4, NB), 256>>>(cd3, cd4, dmin, pred);
    stage2_sum_k<<<dim3(49 + 13, NB), 256>>>(pred, be);
    rowmax_k<<<dim3(392 + 98, NB), 256>>>(cd3, cd4, dmin, be, rm3, rm4);
    final_k<<<1, 256>>>(rm3, rm4, (float*)d_out);
}